// round 4
// baseline (speedup 1.0000x reference)
#include <cuda_runtime.h>
#include <cstdint>
#include <cstddef>

#define BB 64
#define GG 640
#define DD 256
#define HH 8
#define DHH 32
#define NEGINF (-1e9f)

// ---------------- scratch (static __device__, no allocs) ----------------
__device__ float g_gkey[(size_t)BB * HH * DHH * GG];  // [B][H][dh][G]
__device__ float g_gval[(size_t)BB * HH * GG * DHH];  // [B][H][G][dh]
__device__ float g_lk  [(size_t)BB * DD * GG];        // [B][D][G]
__device__ float g_gemb [BB * DD];                    // graph embedding (mean)
__device__ float g_fixed[BB * DD];                    // fixed_ctx

// ---------------- kernel 1: graph mean + fixed context ----------------
__global__ void mean_fixed_kernel(const float* __restrict__ emb,
                                  const float* __restrict__ Wfixed) {
    int b = blockIdx.x;
    int tid = threadIdx.x;  // 256 threads, one per d
    __shared__ float ge[DD];
    const float* e = emb + (size_t)b * GG * DD;
    float acc = 0.f;
    #pragma unroll 4
    for (int g = 0; g < GG; ++g) acc += e[(size_t)g * DD + tid];
    float m = acc * (1.0f / (float)GG);
    ge[tid] = m;
    g_gemb[b * DD + tid] = m;
    __syncthreads();
    float f = 0.f;
    #pragma unroll 4
    for (int i = 0; i < DD; ++i) f = fmaf(ge[i], Wfixed[i * DD + tid], f);
    g_fixed[b * DD + tid] = f;
}

// ---------------- kernel 2: kvl GEMM  [40960,256]x[256,768] with scatter epilogue
// tiles: BM=64 BN=64 BK=32, 256 threads, 4x4 microtile
__global__ void __launch_bounds__(256) kvl_gemm(const float* __restrict__ A,
                                                const float* __restrict__ W) {
    __shared__ float As[32][65];   // [k][m], padded
    __shared__ float Bs[32][68];   // [k][n], padded (row stride 272B, 16B aligned)
    const int bn = blockIdx.x * 64;   // 0..704
    const int bm = blockIdx.y * 64;   // 0..40896
    const int tid = threadIdx.x;
    const int tx = tid & 15, ty = tid >> 4;

    float acc[4][4];
    #pragma unroll
    for (int i = 0; i < 4; ++i)
        #pragma unroll
        for (int j = 0; j < 4; ++j) acc[i][j] = 0.f;

    for (int k0 = 0; k0 < DD; k0 += 32) {
        // load A tile 64x32 (512 float4, 2 per thread), store transposed
        #pragma unroll
        for (int l = 0; l < 2; ++l) {
            int idx = tid * 2 + l;
            int r = idx >> 3, c4 = idx & 7;
            float4 v = *(const float4*)(A + (size_t)(bm + r) * DD + k0 + c4 * 4);
            As[c4 * 4 + 0][r] = v.x;
            As[c4 * 4 + 1][r] = v.y;
            As[c4 * 4 + 2][r] = v.z;
            As[c4 * 4 + 3][r] = v.w;
        }
        // load B tile 32x64 (512 float4, 2 per thread)
        #pragma unroll
        for (int l = 0; l < 2; ++l) {
            int idx = tid * 2 + l;
            int r = idx >> 4, c4 = idx & 15;
            float4 v = *(const float4*)(W + (size_t)(k0 + r) * 768 + bn + c4 * 4);
            *(float4*)&Bs[r][c4 * 4] = v;
        }
        __syncthreads();
        #pragma unroll
        for (int k = 0; k < 32; ++k) {
            float a[4], bb[4];
            #pragma unroll
            for (int i = 0; i < 4; ++i) a[i] = As[k][ty * 4 + i];
            #pragma unroll
            for (int j = 0; j < 4; ++j) bb[j] = Bs[k][tx * 4 + j];
            #pragma unroll
            for (int i = 0; i < 4; ++i)
                #pragma unroll
                for (int j = 0; j < 4; ++j) acc[i][j] = fmaf(a[i], bb[j], acc[i][j]);
        }
        __syncthreads();
    }
    // scatter epilogue to the three consumer layouts
    #pragma unroll
    for (int i = 0; i < 4; ++i) {
        int m = bm + ty * 4 + i;
        int b = m / GG, g = m % GG;
        #pragma unroll
        for (int j = 0; j < 4; ++j) {
            int n = bn + tx * 4 + j;
            float v = acc[i][j];
            if (n < 256) {                       // glimpse key  -> [B][H][dh][G]
                int h = n >> 5, d = n & 31;
                g_gkey[(((size_t)b * HH + h) * DHH + d) * GG + g] = v;
            } else if (n < 512) {                // glimpse val  -> [B][H][G][dh]
                int j2 = n - 256;
                int h = j2 >> 5, d = j2 & 31;
                g_gval[(((size_t)b * HH + h) * GG + g) * DHH + d] = v;
            } else {                             // logit key    -> [B][D][G]
                int d2 = n - 512;
                g_lk[((size_t)b * DD + d2) * GG + g] = v;
            }
        }
    }
}

// ---------------- kernel 3: the 512-step decode loop, one CTA per batch row
__global__ void __launch_bounds__(640, 1) decode_kernel(
    const float* __restrict__ emb, const float* __restrict__ Wstep,
    const float* __restrict__ Wout, const int* __restrict__ n_steps_p,
    float* __restrict__ out, int has_pi) {

    const int b = blockIdx.x;
    const int tid = threadIdx.x;            // 640 threads = 20 warps
    const int warp = tid >> 5, lane = tid & 31;
    const int T = n_steps_p[0];

    __shared__ float fixed_s[DD], prev_s[DD], q_s[DD], heads_s[DD], glimpse_s[DD];
    __shared__ float w_s[HH][GG];           // compat -> exp weights
    __shared__ float logits_s[GG];
    __shared__ float hpart[16][DHH];
    __shared__ float rmax_s[HH], rsum_s[HH];
    __shared__ float red_s[20];
    __shared__ int   red_i[20];
    __shared__ float maxv_s, lse_s;
    __shared__ int   sel_s;
    __shared__ unsigned char visited_s[GG];

    if (tid < DD) {
        fixed_s[tid] = g_fixed[b * DD + tid];
        prev_s[tid]  = g_gemb[b * DD + tid];
    }
    visited_s[tid] = 0;
    __syncthreads();

    const float* gk_b  = g_gkey + (size_t)b * HH * DHH * GG;
    const float* gv_b  = g_gval + (size_t)b * HH * GG * DHH;
    const float* lk_b  = g_lk   + (size_t)b * DD * GG;
    const float* emb_b = emb    + (size_t)b * GG * DD;
    const float inv_sqrt_dh = 0.17677669529663687f;   // 1/sqrt(32)
    const float inv_sqrt_D  = 0.0625f;                // 1/sqrt(256)

    for (int t = 0; t < T; ++t) {
        // ---- q = fixed_ctx + prev_embed @ W_step ----
        if (tid < DD) {
            float acc = 0.f;
            #pragma unroll 4
            for (int i = 0; i < DD; ++i) acc = fmaf(prev_s[i], Wstep[i * DD + tid], acc);
            q_s[tid] = fixed_s[tid] + acc;
        }
        __syncthreads();

        // ---- compat[h][g] = q_h . k[h][g] / sqrt(dh), masked ----
        {
            const int g = tid;
            const bool vis = visited_s[g] != 0;
            #pragma unroll
            for (int h = 0; h < HH; ++h) {
                const float* col = gk_b + (size_t)(h * DHH) * GG + g;
                const float* qh = q_s + h * DHH;
                float acc = 0.f;
                #pragma unroll
                for (int d = 0; d < DHH; ++d) acc = fmaf(qh[d], col[(size_t)d * GG], acc);
                w_s[h][g] = vis ? NEGINF : acc * inv_sqrt_dh;
            }
        }
        __syncthreads();

        // ---- softmax (unnormalized): row max ----
        if (warp < 16) {
            int h = warp >> 1, half = warp & 1;
            const float* row = &w_s[h][half * 320];
            float m = -3e38f;
            #pragma unroll
            for (int k = 0; k < 10; ++k) m = fmaxf(m, row[lane + k * 32]);
            #pragma unroll
            for (int o = 16; o; o >>= 1) m = fmaxf(m, __shfl_xor_sync(0xffffffffu, m, o));
            if (lane == 0) red_s[warp] = m;
        }
        __syncthreads();
        if (tid < HH) rmax_s[tid] = fmaxf(red_s[tid * 2], red_s[tid * 2 + 1]);
        __syncthreads();
        // ---- exp + row sum ----
        if (warp < 16) {
            int h = warp >> 1, half = warp & 1;
            float rm = rmax_s[h];
            float* row = &w_s[h][half * 320];
            float s = 0.f;
            #pragma unroll
            for (int k = 0; k < 10; ++k) {
                float e = expf(row[lane + k * 32] - rm);
                row[lane + k * 32] = e;
                s += e;
            }
            #pragma unroll
            for (int o = 16; o; o >>= 1) s += __shfl_xor_sync(0xffffffffu, s, o);
            if (lane == 0) red_s[warp] = s;
        }
        __syncthreads();
        if (tid < HH) rsum_s[tid] = red_s[tid * 2] + red_s[tid * 2 + 1];
        __syncthreads();

        // ---- heads[h][d] = sum_g w[h][g]*v[h][g][d] / rsum[h] ----
        if (warp < 16) {
            int h = warp >> 1, half = warp & 1;
            const float* vrow = gv_b + ((size_t)h * GG + half * 320) * DHH + lane;
            const float* wrow = &w_s[h][half * 320];
            float acc = 0.f;
            #pragma unroll 4
            for (int g2 = 0; g2 < 320; ++g2) acc = fmaf(wrow[g2], vrow[(size_t)g2 * DHH], acc);
            hpart[warp][lane] = acc;
        }
        __syncthreads();
        if (tid < DD) {
            int h = tid >> 5, d = tid & 31;
            heads_s[tid] = (hpart[h * 2][d] + hpart[h * 2 + 1][d]) / rsum_s[h];
        }
        __syncthreads();

        // ---- glimpse = heads @ W_out ----
        if (tid < DD) {
            float acc = 0.f;
            #pragma unroll 4
            for (int i = 0; i < DD; ++i) acc = fmaf(heads_s[i], Wout[i * DD + tid], acc);
            glimpse_s[tid] = acc;
        }
        __syncthreads();

        // ---- logits[g] = 10*tanh(glimpse . lk[:,g] / sqrt(D)), masked ----
        {
            const int g = tid;
            const float* col = lk_b + g;
            float acc = 0.f;
            #pragma unroll 4
            for (int d = 0; d < DD; ++d) acc = fmaf(glimpse_s[d], col[(size_t)d * GG], acc);
            float l = 10.0f * tanhf(acc * inv_sqrt_D);
            logits_s[g] = visited_s[g] ? NEGINF : l;
        }
        __syncthreads();

        // ---- argmax (first occurrence) + max ----
        {
            float v = logits_s[tid];
            int idx = tid;
            #pragma unroll
            for (int o = 16; o; o >>= 1) {
                float ov = __shfl_xor_sync(0xffffffffu, v, o);
                int oi = __shfl_xor_sync(0xffffffffu, idx, o);
                if (ov > v || (ov == v && oi < idx)) { v = ov; idx = oi; }
            }
            if (lane == 0) { red_s[warp] = v; red_i[warp] = idx; }
        }
        __syncthreads();
        if (tid == 0) {
            float v = red_s[0]; int idx = red_i[0];
            #pragma unroll
            for (int wv = 1; wv < 20; ++wv) {
                if (red_s[wv] > v || (red_s[wv] == v && red_i[wv] < idx)) {
                    v = red_s[wv]; idx = red_i[wv];
                }
            }
            sel_s = idx;
            maxv_s = v;
        }
        __syncthreads();
        const float maxv = maxv_s;
        // ---- logsumexp ----
        {
            float e = expf(logits_s[tid] - maxv);
            #pragma unroll
            for (int o = 16; o; o >>= 1) e += __shfl_xor_sync(0xffffffffu, e, o);
            if (lane == 0) red_s[warp] = e;
        }
        __syncthreads();
        if (tid == 0) {
            float s = 0.f;
            #pragma unroll
            for (int wv = 0; wv < 20; ++wv) s += red_s[wv];
            lse_s = maxv + logf(s);
        }
        __syncthreads();
        const float lse = lse_s;
        const int sel = sel_s;

        // ---- outputs ----
        out[((size_t)b * T + t) * GG + tid] = logits_s[tid] - lse;
        if (has_pi && tid == 0)
            out[(size_t)BB * T * GG + (size_t)b * T + t] = (float)sel;

        // ---- state update ----
        if (tid == 0) visited_s[sel] = 1;
        if (tid < DD) prev_s[tid] = emb_b[(size_t)sel * DD + tid];
        __syncthreads();
    }
}

// ---------------- launch ----------------
extern "C" void kernel_launch(void* const* d_in, const int* in_sizes, int n_in,
                              void* d_out, int out_size) {
    const float* emb    = (const float*)d_in[0];
    const float* Wnode  = (const float*)d_in[1];
    const float* Wfixed = (const float*)d_in[2];
    const float* Wstep  = (const float*)d_in[3];
    const float* Wout   = (const float*)d_in[4];
    const int*   nsteps = (const int*)d_in[5];
    float* out = (float*)d_out;

    // out holds log_p [B,T,G] (+ optionally pi [B,T] as float):
    // B*T*(G+1) = 41024*T  vs  B*T*G = 40960*T. 41024 | out_size <=> pi present (T<641).
    int has_pi = (out_size % (BB * (GG + 1)) == 0) ? 1 : 0;

    mean_fixed_kernel<<<BB, DD>>>(emb, Wfixed);

    dim3 ggrid(12, 640);      // 768/64 x 40960/64
    kvl_gemm<<<ggrid, 256>>>(emb, Wnode);

    decode_kernel<<<BB, GG>>>(emb, Wstep, Wout, nsteps, out, has_pi);
}

// round 6
// speedup vs baseline: 3.9511x; 3.9511x over previous
#include <cuda_runtime.h>
#include <cstdint>
#include <cstddef>

#define BB 64
#define GG 640
#define DD 256
#define HH 8
#define DHH 32
#define NEGINF (-1e9f)

// ---------------- scratch (static __device__, no allocs) ----------------
__device__ float g_gkey[(size_t)BB * HH * DHH * GG];  // [B][H][dh][G]
__device__ float g_gval[(size_t)BB * HH * DHH * GG];  // [B][H][dh][G]  (d-major now!)
__device__ float g_lk  [(size_t)BB * DD * GG];        // [B][D][G]
__device__ float g_gemb [BB * DD];                    // graph embedding (mean)
__device__ float g_fixed[BB * DD];                    // fixed_ctx

// ---------------- kernel 1: graph mean + fixed context ----------------
__global__ void mean_fixed_kernel(const float* __restrict__ emb,
                                  const float* __restrict__ Wfixed) {
    int b = blockIdx.x;
    int tid = threadIdx.x;  // 256 threads, one per d
    __shared__ float ge[DD];
    const float* e = emb + (size_t)b * GG * DD;
    float a0 = 0.f, a1 = 0.f, a2 = 0.f, a3 = 0.f;
    #pragma unroll 4
    for (int g = 0; g < GG; g += 4) {
        a0 += e[(size_t)(g + 0) * DD + tid];
        a1 += e[(size_t)(g + 1) * DD + tid];
        a2 += e[(size_t)(g + 2) * DD + tid];
        a3 += e[(size_t)(g + 3) * DD + tid];
    }
    float m = ((a0 + a1) + (a2 + a3)) * (1.0f / (float)GG);
    ge[tid] = m;
    g_gemb[b * DD + tid] = m;
    __syncthreads();
    float f0 = 0.f, f1 = 0.f, f2 = 0.f, f3 = 0.f;
    #pragma unroll 8
    for (int i = 0; i < DD; i += 4) {
        f0 = fmaf(ge[i + 0], Wfixed[(i + 0) * DD + tid], f0);
        f1 = fmaf(ge[i + 1], Wfixed[(i + 1) * DD + tid], f1);
        f2 = fmaf(ge[i + 2], Wfixed[(i + 2) * DD + tid], f2);
        f3 = fmaf(ge[i + 3], Wfixed[(i + 3) * DD + tid], f3);
    }
    g_fixed[b * DD + tid] = (f0 + f1) + (f2 + f3);
}

// ---------------- kernel 2: kvl GEMM  [40960,256]x[256,768] with scatter epilogue
__global__ void __launch_bounds__(256) kvl_gemm(const float* __restrict__ A,
                                                const float* __restrict__ W) {
    __shared__ float As[32][65];   // [k][m], padded
    __shared__ float Bs[32][68];   // [k][n], padded
    const int bn = blockIdx.x * 64;
    const int bm = blockIdx.y * 64;
    const int tid = threadIdx.x;
    const int tx = tid & 15, ty = tid >> 4;

    float acc[4][4];
    #pragma unroll
    for (int i = 0; i < 4; ++i)
        #pragma unroll
        for (int j = 0; j < 4; ++j) acc[i][j] = 0.f;

    for (int k0 = 0; k0 < DD; k0 += 32) {
        #pragma unroll
        for (int l = 0; l < 2; ++l) {
            int idx = tid * 2 + l;
            int r = idx >> 3, c4 = idx & 7;
            float4 v = *(const float4*)(A + (size_t)(bm + r) * DD + k0 + c4 * 4);
            As[c4 * 4 + 0][r] = v.x;
            As[c4 * 4 + 1][r] = v.y;
            As[c4 * 4 + 2][r] = v.z;
            As[c4 * 4 + 3][r] = v.w;
        }
        #pragma unroll
        for (int l = 0; l < 2; ++l) {
            int idx = tid * 2 + l;
            int r = idx >> 4, c4 = idx & 15;
            float4 v = *(const float4*)(W + (size_t)(k0 + r) * 768 + bn + c4 * 4);
            *(float4*)&Bs[r][c4 * 4] = v;
        }
        __syncthreads();
        #pragma unroll
        for (int k = 0; k < 32; ++k) {
            float a[4], bb[4];
            #pragma unroll
            for (int i = 0; i < 4; ++i) a[i] = As[k][ty * 4 + i];
            #pragma unroll
            for (int j = 0; j < 4; ++j) bb[j] = Bs[k][tx * 4 + j];
            #pragma unroll
            for (int i = 0; i < 4; ++i)
                #pragma unroll
                for (int j = 0; j < 4; ++j) acc[i][j] = fmaf(a[i], bb[j], acc[i][j]);
        }
        __syncthreads();
    }
    #pragma unroll
    for (int i = 0; i < 4; ++i) {
        int m = bm + ty * 4 + i;
        int b = m / GG, g = m % GG;
        #pragma unroll
        for (int j = 0; j < 4; ++j) {
            int n = bn + tx * 4 + j;
            float v = acc[i][j];
            if (n < 256) {                       // glimpse key  -> [B][H][dh][G]
                int h = n >> 5, d = n & 31;
                g_gkey[(((size_t)b * HH + h) * DHH + d) * GG + g] = v;
            } else if (n < 512) {                // glimpse val  -> [B][H][dh][G]
                int j2 = n - 256;
                int h = j2 >> 5, d = j2 & 31;
                g_gval[(((size_t)b * HH + h) * DHH + d) * GG + g] = v;
            } else {                             // logit key    -> [B][D][G]
                int d2 = n - 512;
                g_lk[((size_t)b * DD + d2) * GG + g] = v;
            }
        }
    }
}

// ---------------- kernel 3: the 512-step decode loop, one CTA per batch row
__global__ void __launch_bounds__(640, 1) decode_kernel(
    const float* __restrict__ emb, const float* __restrict__ Wstep,
    const float* __restrict__ Wout, const int* __restrict__ n_steps_p,
    float* __restrict__ out, int has_pi) {

    const int b = blockIdx.x;
    const int tid = threadIdx.x;            // 640 threads = 20 warps
    const int warp = tid >> 5, lane = tid & 31;
    const int T = n_steps_p[0];

    __shared__ float fixed_s[DD], prev_s[DD], q_s[DD], heads_s[DD], glimpse_s[DD];
    __shared__ float w_s[HH][GG];           // compat -> exp weights (20 KB)
    __shared__ float lpart[4][GG];          // logit partials (10 KB)
    __shared__ float qpart[2][DD];
    __shared__ float hpart[2][DD];
    __shared__ float logits_s[GG];
    __shared__ float rmax_s[HH], rsum_s[HH];
    __shared__ float red_s[20];
    __shared__ int   red_i[20];
    __shared__ float maxv_s, lse_s;
    __shared__ int   sel_s;
    __shared__ unsigned char visited_s[GG];

    if (tid < DD) {
        fixed_s[tid] = g_fixed[b * DD + tid];
        prev_s[tid]  = g_gemb[b * DD + tid];
    }
    visited_s[tid] = 0;
    __syncthreads();

    const float* gk_b  = g_gkey + (size_t)b * HH * DHH * GG;
    const float* gv_b  = g_gval + (size_t)b * HH * DHH * GG;
    const float* lk_b  = g_lk   + (size_t)b * DD * GG;
    const float* emb_b = emb    + (size_t)b * GG * DD;
    const float inv_sqrt_dh = 0.17677669529663687f;   // 1/sqrt(32)
    const float inv_sqrt_D  = 0.0625f;                // 1/sqrt(256)

    // thread -> (group, g-quad) decomposition used by compat and logits
    const int grp = tid / 160;        // 0..3
    const int g4  = (tid % 160) * 4;  // 0,4,...,636

    for (int t = 0; t < T; ++t) {
        // ---- q = fixed_ctx + prev_embed @ W_step  (512 threads, split-K by 2) ----
        if (tid < 512) {
            const int part = tid >> 8, col = tid & 255;
            const float* wp = Wstep + (size_t)(part * 128) * DD + col;
            const float* pv = prev_s + part * 128;
            float a0 = 0.f, a1 = 0.f, a2 = 0.f, a3 = 0.f;
            #pragma unroll 8
            for (int i = 0; i < 128; i += 4) {
                a0 = fmaf(pv[i + 0], wp[(size_t)(i + 0) * DD], a0);
                a1 = fmaf(pv[i + 1], wp[(size_t)(i + 1) * DD], a1);
                a2 = fmaf(pv[i + 2], wp[(size_t)(i + 2) * DD], a2);
                a3 = fmaf(pv[i + 3], wp[(size_t)(i + 3) * DD], a3);
            }
            qpart[part][col] = (a0 + a1) + (a2 + a3);
        }
        __syncthreads();
        if (tid < DD) q_s[tid] = fixed_s[tid] + qpart[0][tid] + qpart[1][tid];
        __syncthreads();

        // ---- compat[h][g] = q_h . k[h][:, g] / sqrt(dh), masked ----
        // 640 threads = 4 head-pairs x 160 g-quads; float4 along G
        {
            unsigned char v0 = visited_s[g4 + 0], v1 = visited_s[g4 + 1];
            unsigned char v2 = visited_s[g4 + 2], v3 = visited_s[g4 + 3];
            #pragma unroll
            for (int hh = 0; hh < 2; ++hh) {
                const int h = grp * 2 + hh;
                const float* base = gk_b + (size_t)h * DHH * GG + g4;
                const float* qh = q_s + h * DHH;
                float ax = 0.f, ay = 0.f, az = 0.f, aw = 0.f;
                #pragma unroll
                for (int d = 0; d < DHH; ++d) {
                    float4 kk = *(const float4*)(base + (size_t)d * GG);
                    float qd = qh[d];
                    ax = fmaf(qd, kk.x, ax);
                    ay = fmaf(qd, kk.y, ay);
                    az = fmaf(qd, kk.z, az);
                    aw = fmaf(qd, kk.w, aw);
                }
                float4 r;
                r.x = v0 ? NEGINF : ax * inv_sqrt_dh;
                r.y = v1 ? NEGINF : ay * inv_sqrt_dh;
                r.z = v2 ? NEGINF : az * inv_sqrt_dh;
                r.w = v3 ? NEGINF : aw * inv_sqrt_dh;
                *(float4*)&w_s[h][g4] = r;
            }
        }
        __syncthreads();

        // ---- softmax row max ----
        if (warp < 16) {
            const int h = warp >> 1, half = warp & 1;
            const float* row = &w_s[h][half * 320];
            float m = -3e38f;
            #pragma unroll
            for (int k = 0; k < 10; ++k) m = fmaxf(m, row[lane + k * 32]);
            #pragma unroll
            for (int o = 16; o; o >>= 1) m = fmaxf(m, __shfl_xor_sync(0xffffffffu, m, o));
            if (lane == 0) red_s[warp] = m;
        }
        __syncthreads();
        if (tid < HH) rmax_s[tid] = fmaxf(red_s[tid * 2], red_s[tid * 2 + 1]);
        __syncthreads();
        // ---- exp + row sum ----
        if (warp < 16) {
            const int h = warp >> 1, half = warp & 1;
            const float rm = rmax_s[h];
            float* row = &w_s[h][half * 320];
            float s = 0.f;
            #pragma unroll
            for (int k = 0; k < 10; ++k) {
                float e = expf(row[lane + k * 32] - rm);
                row[lane + k * 32] = e;
                s += e;
            }
            #pragma unroll
            for (int o = 16; o; o >>= 1) s += __shfl_xor_sync(0xffffffffu, s, o);
            if (lane == 0) red_s[warp] = s;
        }
        __syncthreads();
        if (tid < HH) rsum_s[tid] = red_s[tid * 2] + red_s[tid * 2 + 1];
        __syncthreads();

        // ---- heads[h][d] = sum_g w[h][g]*v[h][d][g] / rsum[h] ----
        // 512 threads = 2 g-halves x (h,d); float4 along G, w broadcast from smem
        if (tid < 512) {
            const int part = tid >> 8;
            const int hd = tid & 255;
            const int h = hd >> 5, d = hd & 31;
            const float* vbase = gv_b + ((size_t)h * DHH + d) * GG + part * 320;
            const float* wrow  = &w_s[h][part * 320];
            float ax = 0.f, ay = 0.f, az = 0.f, aw = 0.f;
            #pragma unroll 8
            for (int g2 = 0; g2 < 80; ++g2) {
                float4 vv = *(const float4*)(vbase + g2 * 4);
                float4 ww = *(const float4*)(wrow + g2 * 4);
                ax = fmaf(ww.x, vv.x, ax);
                ay = fmaf(ww.y, vv.y, ay);
                az = fmaf(ww.z, vv.z, az);
                aw = fmaf(ww.w, vv.w, aw);
            }
            hpart[part][hd] = (ax + ay) + (az + aw);
        }
        __syncthreads();
        if (tid < DD) {
            const int h = tid >> 5;
            heads_s[tid] = (hpart[0][tid] + hpart[1][tid]) / rsum_s[h];
        }
        __syncthreads();

        // ---- glimpse = heads @ W_out  (512 threads, split-K by 2) ----
        if (tid < 512) {
            const int part = tid >> 8, col = tid & 255;
            const float* wp = Wout + (size_t)(part * 128) * DD + col;
            const float* hv = heads_s + part * 128;
            float a0 = 0.f, a1 = 0.f, a2 = 0.f, a3 = 0.f;
            #pragma unroll 8
            for (int i = 0; i < 128; i += 4) {
                a0 = fmaf(hv[i + 0], wp[(size_t)(i + 0) * DD], a0);
                a1 = fmaf(hv[i + 1], wp[(size_t)(i + 1) * DD], a1);
                a2 = fmaf(hv[i + 2], wp[(size_t)(i + 2) * DD], a2);
                a3 = fmaf(hv[i + 3], wp[(size_t)(i + 3) * DD], a3);
            }
            qpart[part][col] = (a0 + a1) + (a2 + a3);
        }
        __syncthreads();
        if (tid < DD) glimpse_s[tid] = qpart[0][tid] + qpart[1][tid];
        __syncthreads();

        // ---- logits[g] partials: 4 d-groups x 160 g-quads; float4 along G ----
        {
            const float* base = lk_b + (size_t)(grp * 64) * GG + g4;
            const float* gl = glimpse_s + grp * 64;
            float ax = 0.f, ay = 0.f, az = 0.f, aw = 0.f;
            #pragma unroll 8
            for (int d = 0; d < 64; ++d) {
                float4 kk = *(const float4*)(base + (size_t)d * GG);
                float gv2 = gl[d];
                ax = fmaf(gv2, kk.x, ax);
                ay = fmaf(gv2, kk.y, ay);
                az = fmaf(gv2, kk.z, az);
                aw = fmaf(gv2, kk.w, aw);
            }
            float4 r; r.x = ax; r.y = ay; r.z = az; r.w = aw;
            *(float4*)&lpart[grp][g4] = r;
        }
        __syncthreads();
        {
            float l = (lpart[0][tid] + lpart[1][tid]) + (lpart[2][tid] + lpart[3][tid]);
            l = 10.0f * tanhf(l * inv_sqrt_D);
            logits_s[tid] = visited_s[tid] ? NEGINF : l;
        }
        __syncthreads();

        // ---- argmax (first occurrence) + max ----
        {
            float v = logits_s[tid];
            int idx = tid;
            #pragma unroll
            for (int o = 16; o; o >>= 1) {
                float ov = __shfl_xor_sync(0xffffffffu, v, o);
                int oi = __shfl_xor_sync(0xffffffffu, idx, o);
                if (ov > v || (ov == v && oi < idx)) { v = ov; idx = oi; }
            }
            if (lane == 0) { red_s[warp] = v; red_i[warp] = idx; }
        }
        __syncthreads();
        if (tid == 0) {
            float v = red_s[0]; int idx = red_i[0];
            #pragma unroll
            for (int wv = 1; wv < 20; ++wv) {
                if (red_s[wv] > v || (red_s[wv] == v && red_i[wv] < idx)) {
                    v = red_s[wv]; idx = red_i[wv];
                }
            }
            sel_s = idx;
            maxv_s = v;
        }
        __syncthreads();
        const float maxv = maxv_s;
        // ---- logsumexp ----
        {
            float e = expf(logits_s[tid] - maxv);
            #pragma unroll
            for (int o = 16; o; o >>= 1) e += __shfl_xor_sync(0xffffffffu, e, o);
            if (lane == 0) red_s[warp] = e;
        }
        __syncthreads();
        if (tid == 0) {
            float s = 0.f;
            #pragma unroll
            for (int wv = 0; wv < 20; ++wv) s += red_s[wv];
            lse_s = maxv + logf(s);
        }
        __syncthreads();
        const float lse = lse_s;
        const int sel = sel_s;

        // ---- outputs (streaming stores: don't pollute L2) ----
        __stcs(&out[((size_t)b * T + t) * GG + tid], logits_s[tid] - lse);
        if (has_pi && tid == 0)
            __stcs(&out[(size_t)BB * T * GG + (size_t)b * T + t], (float)sel);

        // ---- state update ----
        if (tid == 0) visited_s[sel] = 1;
        if (tid < DD) prev_s[tid] = __ldg(&emb_b[(size_t)sel * DD + tid]);
        __syncthreads();
    }
}

// ---------------- launch ----------------
extern "C" void kernel_launch(void* const* d_in, const int* in_sizes, int n_in,
                              void* d_out, int out_size) {
    const float* emb    = (const float*)d_in[0];
    const float* Wnode  = (const float*)d_in[1];
    const float* Wfixed = (const float*)d_in[2];
    const float* Wstep  = (const float*)d_in[3];
    const float* Wout   = (const float*)d_in[4];
    const int*   nsteps = (const int*)d_in[5];
    float* out = (float*)d_out;

    int has_pi = (out_size % (BB * (GG + 1)) == 0) ? 1 : 0;

    mean_fixed_kernel<<<BB, DD>>>(emb, Wfixed);

    dim3 ggrid(12, 640);      // 768/64 x 40960/64
    kvl_gemm<<<ggrid, 256>>>(emb, Wnode);

    decode_kernel<<<BB, GG>>>(emb, Wstep, Wout, nsteps, out, has_pi);
}

// round 7
// speedup vs baseline: 5.3954x; 1.3655x over previous
#include <cuda_runtime.h>
#include <cstdint>
#include <cstddef>

#define BB 64
#define GG 640
#define DD 256
#define HH 8
#define DHH 32
#define NEGINF (-1e9f)

// ---------------- scratch (static __device__, no allocs) ----------------
__device__ float g_gkey[(size_t)BB * HH * DHH * GG];  // [B][H][dh][G]
__device__ float g_gval[(size_t)BB * HH * DHH * GG];  // [B][H][dh][G]
__device__ float g_lk  [(size_t)BB * DD * GG];        // [B][D][G]
__device__ float g_gemb [BB * DD];
__device__ float g_fixed[BB * DD];

// ---------------- kernel 1: graph mean + fixed context ----------------
__global__ void mean_fixed_kernel(const float* __restrict__ emb,
                                  const float* __restrict__ Wfixed) {
    int b = blockIdx.x;
    int tid = threadIdx.x;  // 256 threads
    __shared__ float ge[DD];
    const float* e = emb + (size_t)b * GG * DD;
    float a0 = 0.f, a1 = 0.f, a2 = 0.f, a3 = 0.f;
    #pragma unroll 4
    for (int g = 0; g < GG; g += 4) {
        a0 += e[(size_t)(g + 0) * DD + tid];
        a1 += e[(size_t)(g + 1) * DD + tid];
        a2 += e[(size_t)(g + 2) * DD + tid];
        a3 += e[(size_t)(g + 3) * DD + tid];
    }
    float m = ((a0 + a1) + (a2 + a3)) * (1.0f / (float)GG);
    ge[tid] = m;
    g_gemb[b * DD + tid] = m;
    __syncthreads();
    float f0 = 0.f, f1 = 0.f, f2 = 0.f, f3 = 0.f;
    #pragma unroll 8
    for (int i = 0; i < DD; i += 4) {
        f0 = fmaf(ge[i + 0], Wfixed[(i + 0) * DD + tid], f0);
        f1 = fmaf(ge[i + 1], Wfixed[(i + 1) * DD + tid], f1);
        f2 = fmaf(ge[i + 2], Wfixed[(i + 2) * DD + tid], f2);
        f3 = fmaf(ge[i + 3], Wfixed[(i + 3) * DD + tid], f3);
    }
    g_fixed[b * DD + tid] = (f0 + f1) + (f2 + f3);
}

// ---------------- kernel 2: kvl GEMM  [40960,256]x[256,768] with scatter epilogue
__global__ void __launch_bounds__(256) kvl_gemm(const float* __restrict__ A,
                                                const float* __restrict__ W) {
    __shared__ float As[32][65];
    __shared__ float Bs[32][68];
    const int bn = blockIdx.x * 64;
    const int bm = blockIdx.y * 64;
    const int tid = threadIdx.x;
    const int tx = tid & 15, ty = tid >> 4;

    float acc[4][4];
    #pragma unroll
    for (int i = 0; i < 4; ++i)
        #pragma unroll
        for (int j = 0; j < 4; ++j) acc[i][j] = 0.f;

    for (int k0 = 0; k0 < DD; k0 += 32) {
        #pragma unroll
        for (int l = 0; l < 2; ++l) {
            int idx = tid * 2 + l;
            int r = idx >> 3, c4 = idx & 7;
            float4 v = *(const float4*)(A + (size_t)(bm + r) * DD + k0 + c4 * 4);
            As[c4 * 4 + 0][r] = v.x;
            As[c4 * 4 + 1][r] = v.y;
            As[c4 * 4 + 2][r] = v.z;
            As[c4 * 4 + 3][r] = v.w;
        }
        #pragma unroll
        for (int l = 0; l < 2; ++l) {
            int idx = tid * 2 + l;
            int r = idx >> 4, c4 = idx & 15;
            float4 v = *(const float4*)(W + (size_t)(k0 + r) * 768 + bn + c4 * 4);
            *(float4*)&Bs[r][c4 * 4] = v;
        }
        __syncthreads();
        #pragma unroll
        for (int k = 0; k < 32; ++k) {
            float a[4], bb[4];
            #pragma unroll
            for (int i = 0; i < 4; ++i) a[i] = As[k][ty * 4 + i];
            #pragma unroll
            for (int j = 0; j < 4; ++j) bb[j] = Bs[k][tx * 4 + j];
            #pragma unroll
            for (int i = 0; i < 4; ++i)
                #pragma unroll
                for (int j = 0; j < 4; ++j) acc[i][j] = fmaf(a[i], bb[j], acc[i][j]);
        }
        __syncthreads();
    }
    #pragma unroll
    for (int i = 0; i < 4; ++i) {
        int m = bm + ty * 4 + i;
        int b = m / GG, g = m % GG;
        #pragma unroll
        for (int j = 0; j < 4; ++j) {
            int n = bn + tx * 4 + j;
            float v = acc[i][j];
            if (n < 256) {
                int h = n >> 5, d = n & 31;
                g_gkey[(((size_t)b * HH + h) * DHH + d) * GG + g] = v;
            } else if (n < 512) {
                int j2 = n - 256;
                int h = j2 >> 5, d = j2 & 31;
                g_gval[(((size_t)b * HH + h) * DHH + d) * GG + g] = v;
            } else {
                int d2 = n - 512;
                g_lk[((size_t)b * DD + d2) * GG + g] = v;
            }
        }
    }
}

// ---------------- kernel 3: 512-step decode loop, one CTA per batch row
__global__ void __launch_bounds__(640, 1) decode_kernel(
    const float* __restrict__ emb, const float* __restrict__ Wstep,
    const float* __restrict__ Wout, const int* __restrict__ n_steps_p,
    float* __restrict__ out, int has_pi) {

    const int b = blockIdx.x;
    const int tid = threadIdx.x;            // 640 threads = 20 warps
    const int warp = tid >> 5, lane = tid & 31;
    const int T = n_steps_p[0];

    __shared__ float fixed_s[DD], prev_s[DD], q_s[DD], heads_s[DD], glimpse_s[DD];
    __shared__ float w_s[HH][GG];           // compat->exp weights; rows 0-3 reused as logit partials
    __shared__ float qpart8[8][DD];         // split-K projection partials (8 KB)
    __shared__ float logits_s[GG];
    __shared__ float rmax_s[HH], rsum_s[HH];
    __shared__ float red_s[20];
    __shared__ int   red_i[20];
    __shared__ float maxv_s, lse_s;
    __shared__ int   sel_s;
    __shared__ unsigned char visited_s[GG];

    if (tid < DD) {
        fixed_s[tid] = g_fixed[b * DD + tid];
        prev_s[tid]  = g_gemb[b * DD + tid];
    }
    visited_s[tid] = 0;
    __syncthreads();

    const float* gk_b  = g_gkey + (size_t)b * HH * DHH * GG;
    const float* gv_b  = g_gval + (size_t)b * HH * DHH * GG;
    const float* lk_b  = g_lk   + (size_t)b * DD * GG;
    const float* emb_b = emb    + (size_t)b * GG * DD;
    const float inv_sqrt_dh = 0.17677669529663687f;   // 1/sqrt(32)
    const float inv_sqrt_D  = 0.0625f;                // 1/sqrt(256)

    // thread -> (group, g-quad) decomposition used by compat and logits
    const int grp = tid / 160;        // 0..3
    const int g4  = (tid % 160) * 4;  // 0,4,...,636
    // projection decomposition: 512 threads = 8 k-parts x 64 col-quads
    const int pj_part = tid >> 6;         // 0..9 (use <8 path via tid<512)
    const int pj_cq   = (tid & 63) * 4;   // column quad base

    for (int t = 0; t < T; ++t) {
        // ---- q = fixed_ctx + prev_embed @ W_step  (float4, 8-way split-K) ----
        if (tid < 512) {
            const float* wp = Wstep + (size_t)(pj_part * 32) * DD + pj_cq;
            const float* pv = prev_s + pj_part * 32;
            float4 a0 = make_float4(0.f, 0.f, 0.f, 0.f);
            float4 a1 = make_float4(0.f, 0.f, 0.f, 0.f);
            #pragma unroll
            for (int i = 0; i < 32; i += 2) {
                float p0 = pv[i], p1 = pv[i + 1];
                float4 w0 = *(const float4*)(wp + (size_t)i * DD);
                float4 w1 = *(const float4*)(wp + (size_t)(i + 1) * DD);
                a0.x = fmaf(p0, w0.x, a0.x); a0.y = fmaf(p0, w0.y, a0.y);
                a0.z = fmaf(p0, w0.z, a0.z); a0.w = fmaf(p0, w0.w, a0.w);
                a1.x = fmaf(p1, w1.x, a1.x); a1.y = fmaf(p1, w1.y, a1.y);
                a1.z = fmaf(p1, w1.z, a1.z); a1.w = fmaf(p1, w1.w, a1.w);
            }
            float4 r;
            r.x = a0.x + a1.x; r.y = a0.y + a1.y; r.z = a0.z + a1.z; r.w = a0.w + a1.w;
            *(float4*)&qpart8[pj_part][pj_cq] = r;
        }
        __syncthreads();
        if (tid < DD) {
            float s = 0.f;
            #pragma unroll
            for (int p = 0; p < 8; ++p) s += qpart8[p][tid];
            q_s[tid] = fixed_s[tid] + s;
        }
        __syncthreads();

        // ---- compat[h][g] = q_h . k[h][:, g] / sqrt(dh), masked ----
        {
            unsigned char v0 = visited_s[g4 + 0], v1 = visited_s[g4 + 1];
            unsigned char v2 = visited_s[g4 + 2], v3 = visited_s[g4 + 3];
            #pragma unroll
            for (int hh = 0; hh < 2; ++hh) {
                const int h = grp * 2 + hh;
                const float* base = gk_b + (size_t)h * DHH * GG + g4;
                const float* qh = q_s + h * DHH;
                float ax = 0.f, ay = 0.f, az = 0.f, aw = 0.f;
                #pragma unroll
                for (int d = 0; d < DHH; ++d) {
                    float4 kk = *(const float4*)(base + (size_t)d * GG);
                    float qd = qh[d];
                    ax = fmaf(qd, kk.x, ax);
                    ay = fmaf(qd, kk.y, ay);
                    az = fmaf(qd, kk.z, az);
                    aw = fmaf(qd, kk.w, aw);
                }
                float4 r;
                r.x = v0 ? NEGINF : ax * inv_sqrt_dh;
                r.y = v1 ? NEGINF : ay * inv_sqrt_dh;
                r.z = v2 ? NEGINF : az * inv_sqrt_dh;
                r.w = v3 ? NEGINF : aw * inv_sqrt_dh;
                *(float4*)&w_s[h][g4] = r;
            }
        }
        __syncthreads();

        // ---- softmax row max ----
        if (warp < 16) {
            const int h = warp >> 1, half = warp & 1;
            const float* row = &w_s[h][half * 320];
            float m = -3e38f;
            #pragma unroll
            for (int k = 0; k < 10; ++k) m = fmaxf(m, row[lane + k * 32]);
            #pragma unroll
            for (int o = 16; o; o >>= 1) m = fmaxf(m, __shfl_xor_sync(0xffffffffu, m, o));
            if (lane == 0) red_s[warp] = m;
        }
        __syncthreads();
        if (tid < HH) rmax_s[tid] = fmaxf(red_s[tid * 2], red_s[tid * 2 + 1]);
        __syncthreads();
        // ---- exp + row sum ----
        if (warp < 16) {
            const int h = warp >> 1, half = warp & 1;
            const float rm = rmax_s[h];
            float* row = &w_s[h][half * 320];
            float s = 0.f;
            #pragma unroll
            for (int k = 0; k < 10; ++k) {
                float e = expf(row[lane + k * 32] - rm);
                row[lane + k * 32] = e;
                s += e;
            }
            #pragma unroll
            for (int o = 16; o; o >>= 1) s += __shfl_xor_sync(0xffffffffu, s, o);
            if (lane == 0) red_s[warp] = s;
        }
        __syncthreads();
        if (tid < HH) rsum_s[tid] = red_s[tid * 2] + red_s[tid * 2 + 1];
        __syncthreads();

        // ---- heads[h][d] = sum_g w[h][g]*v[h][d][g] / rsum[h] ----
        // warp-per-row: lanes cover 128 consecutive g per LDG.128 (coalesced),
        // 5 chunks/row, shfl reduce. 16 warps x 16 rows = 256 (h,d) rows.
        if (warp < 16) {
            #pragma unroll 2
            for (int r = 0; r < 16; ++r) {
                const int row = warp * 16 + r;        // row = h*32 + d
                const int h = row >> 5;
                const float* vrow = gv_b + (size_t)row * GG + lane * 4;
                const float* wrow = &w_s[h][lane * 4];
                float ax = 0.f, ay = 0.f, az = 0.f, aw = 0.f;
                #pragma unroll
                for (int c = 0; c < 5; ++c) {
                    float4 vv = *(const float4*)(vrow + c * 128);
                    float4 ww = *(const float4*)(wrow + c * 128);
                    ax = fmaf(ww.x, vv.x, ax);
                    ay = fmaf(ww.y, vv.y, ay);
                    az = fmaf(ww.z, vv.z, az);
                    aw = fmaf(ww.w, vv.w, aw);
                }
                float s = (ax + ay) + (az + aw);
                #pragma unroll
                for (int o = 16; o; o >>= 1) s += __shfl_xor_sync(0xffffffffu, s, o);
                if (lane == 0) heads_s[row] = s / rsum_s[h];
            }
        }
        __syncthreads();

        // ---- glimpse = heads @ W_out  (float4, 8-way split-K) ----
        if (tid < 512) {
            const float* wp = Wout + (size_t)(pj_part * 32) * DD + pj_cq;
            const float* hv = heads_s + pj_part * 32;
            float4 a0 = make_float4(0.f, 0.f, 0.f, 0.f);
            float4 a1 = make_float4(0.f, 0.f, 0.f, 0.f);
            #pragma unroll
            for (int i = 0; i < 32; i += 2) {
                float p0 = hv[i], p1 = hv[i + 1];
                float4 w0 = *(const float4*)(wp + (size_t)i * DD);
                float4 w1 = *(const float4*)(wp + (size_t)(i + 1) * DD);
                a0.x = fmaf(p0, w0.x, a0.x); a0.y = fmaf(p0, w0.y, a0.y);
                a0.z = fmaf(p0, w0.z, a0.z); a0.w = fmaf(p0, w0.w, a0.w);
                a1.x = fmaf(p1, w1.x, a1.x); a1.y = fmaf(p1, w1.y, a1.y);
                a1.z = fmaf(p1, w1.z, a1.z); a1.w = fmaf(p1, w1.w, a1.w);
            }
            float4 r;
            r.x = a0.x + a1.x; r.y = a0.y + a1.y; r.z = a0.z + a1.z; r.w = a0.w + a1.w;
            *(float4*)&qpart8[pj_part][pj_cq] = r;
        }
        __syncthreads();
        if (tid < DD) {
            float s = 0.f;
            #pragma unroll
            for (int p = 0; p < 8; ++p) s += qpart8[p][tid];
            glimpse_s[tid] = s;
        }
        __syncthreads();

        // ---- logits[g] partials: 4 d-groups x 160 g-quads (partials into w_s rows 0-3) ----
        {
            const float* base = lk_b + (size_t)(grp * 64) * GG + g4;
            const float* gl = glimpse_s + grp * 64;
            float ax = 0.f, ay = 0.f, az = 0.f, aw = 0.f;
            #pragma unroll 8
            for (int d = 0; d < 64; ++d) {
                float4 kk = *(const float4*)(base + (size_t)d * GG);
                float gv2 = gl[d];
                ax = fmaf(gv2, kk.x, ax);
                ay = fmaf(gv2, kk.y, ay);
                az = fmaf(gv2, kk.z, az);
                aw = fmaf(gv2, kk.w, aw);
            }
            float4 r; r.x = ax; r.y = ay; r.z = az; r.w = aw;
            *(float4*)&w_s[grp][g4] = r;
        }
        __syncthreads();
        {
            float l = (w_s[0][tid] + w_s[1][tid]) + (w_s[2][tid] + w_s[3][tid]);
            l = 10.0f * tanhf(l * inv_sqrt_D);
            logits_s[tid] = visited_s[tid] ? NEGINF : l;
        }
        __syncthreads();

        // ---- argmax (first occurrence) + max ----
        {
            float v = logits_s[tid];
            int idx = tid;
            #pragma unroll
            for (int o = 16; o; o >>= 1) {
                float ov = __shfl_xor_sync(0xffffffffu, v, o);
                int oi = __shfl_xor_sync(0xffffffffu, idx, o);
                if (ov > v || (ov == v && oi < idx)) { v = ov; idx = oi; }
            }
            if (lane == 0) { red_s[warp] = v; red_i[warp] = idx; }
        }
        __syncthreads();
        if (tid == 0) {
            float v = red_s[0]; int idx = red_i[0];
            #pragma unroll
            for (int wv = 1; wv < 20; ++wv) {
                if (red_s[wv] > v || (red_s[wv] == v && red_i[wv] < idx)) {
                    v = red_s[wv]; idx = red_i[wv];
                }
            }
            sel_s = idx;
            maxv_s = v;
        }
        __syncthreads();
        const float maxv = maxv_s;
        // ---- logsumexp ----
        {
            float e = expf(logits_s[tid] - maxv);
            #pragma unroll
            for (int o = 16; o; o >>= 1) e += __shfl_xor_sync(0xffffffffu, e, o);
            if (lane == 0) red_s[warp] = e;
        }
        __syncthreads();
        if (tid == 0) {
            float s = 0.f;
            #pragma unroll
            for (int wv = 0; wv < 20; ++wv) s += red_s[wv];
            lse_s = maxv + logf(s);
        }
        __syncthreads();
        const float lse = lse_s;
        const int sel = sel_s;

        // ---- outputs (streaming stores) ----
        __stcs(&out[((size_t)b * T + t) * GG + tid], logits_s[tid] - lse);
        if (has_pi && tid == 0)
            __stcs(&out[(size_t)BB * T * GG + (size_t)b * T + t], (float)sel);

        // ---- state update ----
        if (tid == 0) visited_s[sel] = 1;
        if (tid < DD) prev_s[tid] = __ldg(&emb_b[(size_t)sel * DD + tid]);
        __syncthreads();
    }
}

// ---------------- launch ----------------
extern "C" void kernel_launch(void* const* d_in, const int* in_sizes, int n_in,
                              void* d_out, int out_size) {
    const float* emb    = (const float*)d_in[0];
    const float* Wnode  = (const float*)d_in[1];
    const float* Wfixed = (const float*)d_in[2];
    const float* Wstep  = (const float*)d_in[3];
    const float* Wout   = (const float*)d_in[4];
    const int*   nsteps = (const int*)d_in[5];
    float* out = (float*)d_out;

    int has_pi = (out_size % (BB * (GG + 1)) == 0) ? 1 : 0;

    mean_fixed_kernel<<<BB, DD>>>(emb, Wfixed);

    dim3 ggrid(12, 640);      // 768/64 x 40960/64
    kvl_gemm<<<ggrid, 256>>>(emb, Wnode);

    decode_kernel<<<BB, GG>>>(emb, Wstep, Wout, nsteps, out, has_pi);
}

// round 9
// speedup vs baseline: 5.7777x; 1.0709x over previous
#include <cuda_runtime.h>
#include <cooperative_groups.h>
#include <cstdint>
#include <cstddef>

namespace cg = cooperative_groups;

#define BB 64
#define GG 640
#define GH 320
#define DD 256
#define HH 8
#define DHH 32
#define NEGINF (-1e9f)

// ---------------- scratch (static __device__, no allocs) ----------------
__device__ float g_gkey[(size_t)BB * HH * DHH * GG];  // [B][H][dh][G]
__device__ float g_gval[(size_t)BB * HH * DHH * GG];  // [B][H][dh][G]
__device__ float g_lk  [(size_t)BB * DD * GG];        // [B][D][G]
__device__ float g_gemb [BB * DD];
__device__ float g_fixed[BB * DD];

// ---------------- kernel 1: graph mean + fixed context ----------------
__global__ void mean_fixed_kernel(const float* __restrict__ emb,
                                  const float* __restrict__ Wfixed) {
    int b = blockIdx.x;
    int tid = threadIdx.x;  // 256 threads
    __shared__ float ge[DD];
    const float* e = emb + (size_t)b * GG * DD;
    float a0 = 0.f, a1 = 0.f, a2 = 0.f, a3 = 0.f;
    #pragma unroll 4
    for (int g = 0; g < GG; g += 4) {
        a0 += e[(size_t)(g + 0) * DD + tid];
        a1 += e[(size_t)(g + 1) * DD + tid];
        a2 += e[(size_t)(g + 2) * DD + tid];
        a3 += e[(size_t)(g + 3) * DD + tid];
    }
    float m = ((a0 + a1) + (a2 + a3)) * (1.0f / (float)GG);
    ge[tid] = m;
    g_gemb[b * DD + tid] = m;
    __syncthreads();
    float f0 = 0.f, f1 = 0.f, f2 = 0.f, f3 = 0.f;
    #pragma unroll 8
    for (int i = 0; i < DD; i += 4) {
        f0 = fmaf(ge[i + 0], Wfixed[(i + 0) * DD + tid], f0);
        f1 = fmaf(ge[i + 1], Wfixed[(i + 1) * DD + tid], f1);
        f2 = fmaf(ge[i + 2], Wfixed[(i + 2) * DD + tid], f2);
        f3 = fmaf(ge[i + 3], Wfixed[(i + 3) * DD + tid], f3);
    }
    g_fixed[b * DD + tid] = (f0 + f1) + (f2 + f3);
}

// ---------------- kernel 2: kvl GEMM  [40960,256]x[256,768] with scatter epilogue
__global__ void __launch_bounds__(256) kvl_gemm(const float* __restrict__ A,
                                                const float* __restrict__ W) {
    __shared__ float As[32][65];
    __shared__ float Bs[32][68];
    const int bn = blockIdx.x * 64;
    const int bm = blockIdx.y * 64;
    const int tid = threadIdx.x;
    const int tx = tid & 15, ty = tid >> 4;

    float acc[4][4];
    #pragma unroll
    for (int i = 0; i < 4; ++i)
        #pragma unroll
        for (int j = 0; j < 4; ++j) acc[i][j] = 0.f;

    for (int k0 = 0; k0 < DD; k0 += 32) {
        #pragma unroll
        for (int l = 0; l < 2; ++l) {
            int idx = tid * 2 + l;
            int r = idx >> 3, c4 = idx & 7;
            float4 v = *(const float4*)(A + (size_t)(bm + r) * DD + k0 + c4 * 4);
            As[c4 * 4 + 0][r] = v.x;
            As[c4 * 4 + 1][r] = v.y;
            As[c4 * 4 + 2][r] = v.z;
            As[c4 * 4 + 3][r] = v.w;
        }
        #pragma unroll
        for (int l = 0; l < 2; ++l) {
            int idx = tid * 2 + l;
            int r = idx >> 4, c4 = idx & 15;
            float4 v = *(const float4*)(W + (size_t)(k0 + r) * 768 + bn + c4 * 4);
            *(float4*)&Bs[r][c4 * 4] = v;
        }
        __syncthreads();
        #pragma unroll
        for (int k = 0; k < 32; ++k) {
            float a[4], bb[4];
            #pragma unroll
            for (int i = 0; i < 4; ++i) a[i] = As[k][ty * 4 + i];
            #pragma unroll
            for (int j = 0; j < 4; ++j) bb[j] = Bs[k][tx * 4 + j];
            #pragma unroll
            for (int i = 0; i < 4; ++i)
                #pragma unroll
                for (int j = 0; j < 4; ++j) acc[i][j] = fmaf(a[i], bb[j], acc[i][j]);
        }
        __syncthreads();
    }
    #pragma unroll
    for (int i = 0; i < 4; ++i) {
        int m = bm + ty * 4 + i;
        int b = m / GG, g = m % GG;
        #pragma unroll
        for (int j = 0; j < 4; ++j) {
            int n = bn + tx * 4 + j;
            float v = acc[i][j];
            if (n < 256) {
                int h = n >> 5, d = n & 31;
                g_gkey[(((size_t)b * HH + h) * DHH + d) * GG + g] = v;
            } else if (n < 512) {
                int j2 = n - 256;
                int h = j2 >> 5, d = j2 & 31;
                g_gval[(((size_t)b * HH + h) * DHH + d) * GG + g] = v;
            } else {
                int d2 = n - 512;
                g_lk[((size_t)b * DD + d2) * GG + g] = v;
            }
        }
    }
}

// ---------------- kernel 3: 512-step decode, cluster of 2 CTAs per batch row
__global__ void __launch_bounds__(640, 1) __cluster_dims__(2, 1, 1)
decode_kernel(const float* __restrict__ emb, const float* __restrict__ Wstep,
              const float* __restrict__ Wout, const int* __restrict__ n_steps_p,
              float* __restrict__ out, int has_pi) {

    cg::cluster_group cl = cg::this_cluster();
    const int rank = (int)(blockIdx.x & 1);
    const int b = blockIdx.x >> 1;
    const int goff = rank * GH;
    const int tid = threadIdx.x;            // 640 threads = 20 warps
    const int warp = tid >> 5, lane = tid & 31;
    const int T = n_steps_p[0];

    __shared__ float fixed_s[DD], prev_s[DD], q_s[DD], heads_s[DD], glimpse_s[DD];
    __shared__ float w_s[HH][GH];           // compat->exp weights; reused as logit partials
    __shared__ float qpart8[8][DD];         // split-K projection partials
    __shared__ float logits_s[GH];
    __shared__ float rmax_s[HH];
    __shared__ float red_s[20];
    __shared__ int   red_i[20];
    __shared__ float maxv_s, lse_s;
    __shared__ int   sel_s;
    __shared__ unsigned char visited_s[GH];
    // ---- DSMEM exchange buffers (peer reads these) ----
    __shared__ float exc_q[DD];
    __shared__ float exc_heads[DD];
    __shared__ float exc_gl[DD];
    __shared__ float exc_max[HH];
    __shared__ float exc_sum[HH];
    __shared__ float exc_amv;
    __shared__ int   exc_ami;
    __shared__ float exc_ls;

    const int peer = rank ^ 1;
    const float* p_q     = (const float*)cl.map_shared_rank((void*)exc_q, peer);
    const float* p_heads = (const float*)cl.map_shared_rank((void*)exc_heads, peer);
    const float* p_gl    = (const float*)cl.map_shared_rank((void*)exc_gl, peer);
    const float* p_max   = (const float*)cl.map_shared_rank((void*)exc_max, peer);
    const float* p_sum   = (const float*)cl.map_shared_rank((void*)exc_sum, peer);
    const float* p_amv   = (const float*)cl.map_shared_rank((void*)&exc_amv, peer);
    const int*   p_ami   = (const int*)cl.map_shared_rank((void*)&exc_ami, peer);
    const float* p_ls    = (const float*)cl.map_shared_rank((void*)&exc_ls, peer);

    if (tid < DD) {
        fixed_s[tid] = g_fixed[b * DD + tid];
        prev_s[tid]  = g_gemb[b * DD + tid];
    }
    if (tid < GH) visited_s[tid] = 0;
    __syncthreads();

    const float* gk_b  = g_gkey + (size_t)b * HH * DHH * GG + goff;
    const float* gv_b  = g_gval + (size_t)b * HH * DHH * GG + goff;
    const float* lk_b  = g_lk   + (size_t)b * DD * GG + goff;
    const float* emb_b = emb    + (size_t)b * GG * DD;
    const float inv_sqrt_dh = 0.17677669529663687f;   // 1/sqrt(32)
    const float inv_sqrt_D  = 0.0625f;                // 1/sqrt(256)

    // compat/logits decomposition: this CTA covers 320 g's
    const int cp_h  = tid / 80;          // head (compat) / d-group (logits)
    const int cp_g4 = (tid % 80) * 4;    // local g quad base
    // projection decomposition: 512 threads = 8 k-subparts x 64 col-quads (own 128-k half)
    const int pj_p  = tid >> 6;          // 0..9 (used when tid<512)
    const int pj_cq = (tid & 63) * 4;

    for (int t = 0; t < T; ++t) {
        // ======== q = fixed + prev @ Wstep : split-K across cluster ========
        if (tid < 512) {
            const int kbase = rank * 128 + pj_p * 16;
            const float* wp = Wstep + (size_t)kbase * DD + pj_cq;
            const float* pv = prev_s + kbase;
            float4 a0 = make_float4(0.f, 0.f, 0.f, 0.f);
            float4 a1 = make_float4(0.f, 0.f, 0.f, 0.f);
            #pragma unroll
            for (int i = 0; i < 16; i += 2) {
                float v0 = pv[i], v1 = pv[i + 1];
                float4 w0 = *(const float4*)(wp + (size_t)i * DD);
                float4 w1 = *(const float4*)(wp + (size_t)(i + 1) * DD);
                a0.x = fmaf(v0, w0.x, a0.x); a0.y = fmaf(v0, w0.y, a0.y);
                a0.z = fmaf(v0, w0.z, a0.z); a0.w = fmaf(v0, w0.w, a0.w);
                a1.x = fmaf(v1, w1.x, a1.x); a1.y = fmaf(v1, w1.y, a1.y);
                a1.z = fmaf(v1, w1.z, a1.z); a1.w = fmaf(v1, w1.w, a1.w);
            }
            float4 r;
            r.x = a0.x + a1.x; r.y = a0.y + a1.y; r.z = a0.z + a1.z; r.w = a0.w + a1.w;
            *(float4*)&qpart8[pj_p][pj_cq] = r;
        }
        __syncthreads();
        if (tid < DD) {
            float s = 0.f;
            #pragma unroll
            for (int p = 0; p < 8; ++p) s += qpart8[p][tid];
            exc_q[tid] = s;
        }
        cl.sync();                                   // S1
        if (tid < DD) {
            float lo = rank == 0 ? exc_q[tid] : p_q[tid];
            float hi = rank == 0 ? p_q[tid] : exc_q[tid];
            q_s[tid] = fixed_s[tid] + lo + hi;       // rank-independent order
        }
        __syncthreads();

        // ======== compat over my 320 g's, all 8 heads ========
        {
            unsigned char v0 = visited_s[cp_g4 + 0], v1 = visited_s[cp_g4 + 1];
            unsigned char v2 = visited_s[cp_g4 + 2], v3 = visited_s[cp_g4 + 3];
            const float* base = gk_b + (size_t)cp_h * DHH * GG + cp_g4;
            const float* qh = q_s + cp_h * DHH;
            float ax = 0.f, ay = 0.f, az = 0.f, aw = 0.f;
            #pragma unroll
            for (int d = 0; d < DHH; ++d) {
                float4 kk = *(const float4*)(base + (size_t)d * GG);
                float qd = qh[d];
                ax = fmaf(qd, kk.x, ax);
                ay = fmaf(qd, kk.y, ay);
                az = fmaf(qd, kk.z, az);
                aw = fmaf(qd, kk.w, aw);
            }
            float4 r;
            r.x = v0 ? NEGINF : ax * inv_sqrt_dh;
            r.y = v1 ? NEGINF : ay * inv_sqrt_dh;
            r.z = v2 ? NEGINF : az * inv_sqrt_dh;
            r.w = v3 ? NEGINF : aw * inv_sqrt_dh;
            *(float4*)&w_s[cp_h][cp_g4] = r;
        }
        __syncthreads();

        // ======== local row max (16 warps: h = w>>1, 160 each) ========
        if (warp < 16) {
            const int h = warp >> 1, half = warp & 1;
            const float* row = &w_s[h][half * 160];
            float m = -3e38f;
            #pragma unroll
            for (int k = 0; k < 5; ++k) m = fmaxf(m, row[lane + k * 32]);
            #pragma unroll
            for (int o = 16; o; o >>= 1) m = fmaxf(m, __shfl_xor_sync(0xffffffffu, m, o));
            if (lane == 0) red_s[warp] = m;
        }
        __syncthreads();
        if (tid < HH) exc_max[tid] = fmaxf(red_s[tid * 2], red_s[tid * 2 + 1]);
        cl.sync();                                   // S2
        if (tid < HH) rmax_s[tid] = fmaxf(exc_max[tid], p_max[tid]);
        __syncthreads();

        // ======== exp(x - globalmax) + local sums ========
        if (warp < 16) {
            const int h = warp >> 1, half = warp & 1;
            const float rm = rmax_s[h];
            float* row = &w_s[h][half * 160];
            float s = 0.f;
            #pragma unroll
            for (int k = 0; k < 5; ++k) {
                float e = expf(row[lane + k * 32] - rm);
                row[lane + k * 32] = e;
                s += e;
            }
            #pragma unroll
            for (int o = 16; o; o >>= 1) s += __shfl_xor_sync(0xffffffffu, s, o);
            if (lane == 0) red_s[warp] = s;
        }
        __syncthreads();
        if (tid < HH) exc_sum[tid] = red_s[tid * 2] + red_s[tid * 2 + 1];

        // ======== heads partials over my 320 g's (warp-per-row, coalesced) ====
        if (warp < 16) {
            #pragma unroll 2
            for (int r = 0; r < 16; ++r) {
                const int row = warp * 16 + r;        // row = h*32 + d
                const int h = row >> 5;
                const float* vrow = gv_b + (size_t)row * GG;
                const float* wrow = &w_s[h][0];
                float ax = 0.f, ay = 0.f, az = 0.f, aw = 0.f;
                #pragma unroll
                for (int c = 0; c < 3; ++c) {
                    int u = lane + c * 32;            // float4 unit, 80 total
                    if (u < 80) {
                        float4 vv = *(const float4*)(vrow + u * 4);
                        float4 ww = *(const float4*)(wrow + u * 4);
                        ax = fmaf(ww.x, vv.x, ax);
                        ay = fmaf(ww.y, vv.y, ay);
                        az = fmaf(ww.z, vv.z, az);
                        aw = fmaf(ww.w, vv.w, aw);
                    }
                }
                float s = (ax + ay) + (az + aw);
                #pragma unroll
                for (int o = 16; o; o >>= 1) s += __shfl_xor_sync(0xffffffffu, s, o);
                if (lane == 0) exc_heads[row] = s;
            }
        }
        cl.sync();                                   // S3
        if (tid < DD) {
            const int h = tid >> 5;
            float hlo = rank == 0 ? exc_heads[tid] : p_heads[tid];
            float hhi = rank == 0 ? p_heads[tid] : exc_heads[tid];
            float slo = rank == 0 ? exc_sum[h] : p_sum[h];
            float shi = rank == 0 ? p_sum[h] : exc_sum[h];
            heads_s[tid] = (hlo + hhi) / (slo + shi);
        }
        __syncthreads();

        // ======== glimpse = heads @ Wout : split-K across cluster ========
        if (tid < 512) {
            const int kbase = rank * 128 + pj_p * 16;
            const float* wp = Wout + (size_t)kbase * DD + pj_cq;
            const float* hv = heads_s + kbase;
            float4 a0 = make_float4(0.f, 0.f, 0.f, 0.f);
            float4 a1 = make_float4(0.f, 0.f, 0.f, 0.f);
            #pragma unroll
            for (int i = 0; i < 16; i += 2) {
                float v0 = hv[i], v1 = hv[i + 1];
                float4 w0 = *(const float4*)(wp + (size_t)i * DD);
                float4 w1 = *(const float4*)(wp + (size_t)(i + 1) * DD);
                a0.x = fmaf(v0, w0.x, a0.x); a0.y = fmaf(v0, w0.y, a0.y);
                a0.z = fmaf(v0, w0.z, a0.z); a0.w = fmaf(v0, w0.w, a0.w);
                a1.x = fmaf(v1, w1.x, a1.x); a1.y = fmaf(v1, w1.y, a1.y);
                a1.z = fmaf(v1, w1.z, a1.z); a1.w = fmaf(v1, w1.w, a1.w);
            }
            float4 r;
            r.x = a0.x + a1.x; r.y = a0.y + a1.y; r.z = a0.z + a1.z; r.w = a0.w + a1.w;
            *(float4*)&qpart8[pj_p][pj_cq] = r;
        }
        __syncthreads();
        if (tid < DD) {
            float s = 0.f;
            #pragma unroll
            for (int p = 0; p < 8; ++p) s += qpart8[p][tid];
            exc_gl[tid] = s;
        }
        cl.sync();                                   // S4
        if (tid < DD) {
            float lo = rank == 0 ? exc_gl[tid] : p_gl[tid];
            float hi = rank == 0 ? p_gl[tid] : exc_gl[tid];
            glimpse_s[tid] = lo + hi;
        }
        __syncthreads();

        // ======== logits partials: 8 d-groups x 80 g-quads (into w_s) ========
        {
            const float* base = lk_b + (size_t)(cp_h * 32) * GG + cp_g4;
            const float* gl = glimpse_s + cp_h * 32;
            float ax = 0.f, ay = 0.f, az = 0.f, aw = 0.f;
            #pragma unroll 8
            for (int d = 0; d < 32; ++d) {
                float4 kk = *(const float4*)(base + (size_t)d * GG);
                float gv2 = gl[d];
                ax = fmaf(gv2, kk.x, ax);
                ay = fmaf(gv2, kk.y, ay);
                az = fmaf(gv2, kk.z, az);
                aw = fmaf(gv2, kk.w, aw);
            }
            float4 r; r.x = ax; r.y = ay; r.z = az; r.w = aw;
            *(float4*)&w_s[cp_h][cp_g4] = r;
        }
        __syncthreads();
        if (tid < GH) {
            float l = ((w_s[0][tid] + w_s[1][tid]) + (w_s[2][tid] + w_s[3][tid]))
                    + ((w_s[4][tid] + w_s[5][tid]) + (w_s[6][tid] + w_s[7][tid]));
            l = 10.0f * tanhf(l * inv_sqrt_D);
            logits_s[tid] = visited_s[tid] ? NEGINF : l;
        }
        __syncthreads();

        // ======== local argmax over my 320 (first occurrence, global idx) ====
        if (tid < GH) {
            float v = logits_s[tid];
            int idx = goff + tid;
            #pragma unroll
            for (int o = 16; o; o >>= 1) {
                float ov = __shfl_xor_sync(0xffffffffu, v, o);
                int oi = __shfl_xor_sync(0xffffffffu, idx, o);
                if (ov > v || (ov == v && oi < idx)) { v = ov; idx = oi; }
            }
            if (lane == 0) { red_s[warp] = v; red_i[warp] = idx; }
        }
        __syncthreads();
        if (tid == 0) {
            float v = red_s[0]; int idx = red_i[0];
            #pragma unroll
            for (int wv = 1; wv < 10; ++wv) {
                if (red_s[wv] > v || (red_s[wv] == v && red_i[wv] < idx)) {
                    v = red_s[wv]; idx = red_i[wv];
                }
            }
            exc_amv = v; exc_ami = idx;
        }
        cl.sync();                                   // S5
        if (tid == 0) {
            float mv = exc_amv; int mi = exc_ami;
            float ov = *p_amv; int oi = *p_ami;
            if (ov > mv || (ov == mv && oi < mi)) { mv = ov; mi = oi; }
            sel_s = mi; maxv_s = mv;
        }
        __syncthreads();
        const float maxv = maxv_s;
        const int sel = sel_s;

        // ======== logsumexp: local half sums, then combine ========
        if (tid < GH) {
            float e = expf(logits_s[tid] - maxv);
            #pragma unroll
            for (int o = 16; o; o >>= 1) e += __shfl_xor_sync(0xffffffffu, e, o);
            if (lane == 0) red_s[warp] = e;
        }
        __syncthreads();
        if (tid == 0) {
            float s = 0.f;
            #pragma unroll
            for (int wv = 0; wv < 10; ++wv) s += red_s[wv];
            exc_ls = s;
        }
        cl.sync();                                   // S6
        if (tid == 0) {
            float lo = rank == 0 ? exc_ls : *p_ls;
            float hi = rank == 0 ? *p_ls : exc_ls;
            lse_s = maxv + logf(lo + hi);
        }
        __syncthreads();
        const float lse = lse_s;

        // ======== outputs (streaming stores) ========
        if (tid < GH)
            __stcs(&out[((size_t)b * T + t) * GG + goff + tid], logits_s[tid] - lse);
        if (has_pi && rank == 0 && tid == 0)
            __stcs(&out[(size_t)BB * T * GG + (size_t)b * T + t], (float)sel);

        // ======== state update ========
        if (tid == 0 && (sel >> 5) / 10 == rank)     // sel/320 == rank
            visited_s[sel - goff] = 1;
        if (tid < DD) prev_s[tid] = __ldg(&emb_b[(size_t)sel * DD + tid]);
        __syncthreads();
    }
}

// ---------------- launch ----------------
extern "C" void kernel_launch(void* const* d_in, const int* in_sizes, int n_in,
                              void* d_out, int out_size) {
    const float* emb    = (const float*)d_in[0];
    const float* Wnode  = (const float*)d_in[1];
    const float* Wfixed = (const float*)d_in[2];
    const float* Wstep  = (const float*)d_in[3];
    const float* Wout   = (const float*)d_in[4];
    const int*   nsteps = (const int*)d_in[5];
    float* out = (float*)d_out;

    int has_pi = (out_size % (BB * (GG + 1)) == 0) ? 1 : 0;

    mean_fixed_kernel<<<BB, DD>>>(emb, Wfixed);

    dim3 ggrid(12, 640);      // 768/64 x 40960/64
    kvl_gemm<<<ggrid, 256>>>(emb, Wnode);

    decode_kernel<<<BB * 2, GG>>>(emb, Wstep, Wout, nsteps, out, has_pi);
}

// round 10
// speedup vs baseline: 8.3623x; 1.4473x over previous
#include <cuda_runtime.h>
#include <cooperative_groups.h>
#include <cstdint>
#include <cstddef>

namespace cg = cooperative_groups;

#define BB 64
#define GG 640
#define GH 320
#define DD 256
#define HH 8
#define DHH 32
#define NEGINF (-1e9f)

// ---------------- scratch (static __device__, no allocs) ----------------
__device__ float g_gkey[(size_t)BB * HH * DHH * GG];  // [B][H][dh][G]
__device__ float g_gval[(size_t)BB * HH * DHH * GG];  // [B][H][dh][G]
__device__ float g_lk  [(size_t)BB * DD * GG];        // [B][D][G]
__device__ float g_gemb [BB * DD];
__device__ float g_fixed[BB * DD];

// ---------------- kernel 1: graph mean + fixed context ----------------
__global__ void mean_fixed_kernel(const float* __restrict__ emb,
                                  const float* __restrict__ Wfixed) {
    int b = blockIdx.x;
    int tid = threadIdx.x;  // 256 threads
    __shared__ float ge[DD];
    const float* e = emb + (size_t)b * GG * DD;
    float a0 = 0.f, a1 = 0.f, a2 = 0.f, a3 = 0.f;
    #pragma unroll 4
    for (int g = 0; g < GG; g += 4) {
        a0 += e[(size_t)(g + 0) * DD + tid];
        a1 += e[(size_t)(g + 1) * DD + tid];
        a2 += e[(size_t)(g + 2) * DD + tid];
        a3 += e[(size_t)(g + 3) * DD + tid];
    }
    float m = ((a0 + a1) + (a2 + a3)) * (1.0f / (float)GG);
    ge[tid] = m;
    g_gemb[b * DD + tid] = m;
    __syncthreads();
    float f0 = 0.f, f1 = 0.f, f2 = 0.f, f3 = 0.f;
    #pragma unroll 8
    for (int i = 0; i < DD; i += 4) {
        f0 = fmaf(ge[i + 0], Wfixed[(i + 0) * DD + tid], f0);
        f1 = fmaf(ge[i + 1], Wfixed[(i + 1) * DD + tid], f1);
        f2 = fmaf(ge[i + 2], Wfixed[(i + 2) * DD + tid], f2);
        f3 = fmaf(ge[i + 3], Wfixed[(i + 3) * DD + tid], f3);
    }
    g_fixed[b * DD + tid] = (f0 + f1) + (f2 + f3);
}

// ---------------- kernel 2: kvl GEMM  [40960,256]x[256,768] with scatter epilogue
__global__ void __launch_bounds__(256) kvl_gemm(const float* __restrict__ A,
                                                const float* __restrict__ W) {
    __shared__ float As[32][65];
    __shared__ float Bs[32][68];
    const int bn = blockIdx.x * 64;
    const int bm = blockIdx.y * 64;
    const int tid = threadIdx.x;
    const int tx = tid & 15, ty = tid >> 4;

    float acc[4][4];
    #pragma unroll
    for (int i = 0; i < 4; ++i)
        #pragma unroll
        for (int j = 0; j < 4; ++j) acc[i][j] = 0.f;

    for (int k0 = 0; k0 < DD; k0 += 32) {
        #pragma unroll
        for (int l = 0; l < 2; ++l) {
            int idx = tid * 2 + l;
            int r = idx >> 3, c4 = idx & 7;
            float4 v = *(const float4*)(A + (size_t)(bm + r) * DD + k0 + c4 * 4);
            As[c4 * 4 + 0][r] = v.x;
            As[c4 * 4 + 1][r] = v.y;
            As[c4 * 4 + 2][r] = v.z;
            As[c4 * 4 + 3][r] = v.w;
        }
        #pragma unroll
        for (int l = 0; l < 2; ++l) {
            int idx = tid * 2 + l;
            int r = idx >> 4, c4 = idx & 15;
            float4 v = *(const float4*)(W + (size_t)(k0 + r) * 768 + bn + c4 * 4);
            *(float4*)&Bs[r][c4 * 4] = v;
        }
        __syncthreads();
        #pragma unroll
        for (int k = 0; k < 32; ++k) {
            float a[4], bb[4];
            #pragma unroll
            for (int i = 0; i < 4; ++i) a[i] = As[k][ty * 4 + i];
            #pragma unroll
            for (int j = 0; j < 4; ++j) bb[j] = Bs[k][tx * 4 + j];
            #pragma unroll
            for (int i = 0; i < 4; ++i)
                #pragma unroll
                for (int j = 0; j < 4; ++j) acc[i][j] = fmaf(a[i], bb[j], acc[i][j]);
        }
        __syncthreads();
    }
    #pragma unroll
    for (int i = 0; i < 4; ++i) {
        int m = bm + ty * 4 + i;
        int b = m / GG, g = m % GG;
        #pragma unroll
        for (int j = 0; j < 4; ++j) {
            int n = bn + tx * 4 + j;
            float v = acc[i][j];
            if (n < 256) {
                int h = n >> 5, d = n & 31;
                g_gkey[(((size_t)b * HH + h) * DHH + d) * GG + g] = v;
            } else if (n < 512) {
                int j2 = n - 256;
                int h = j2 >> 5, d = j2 & 31;
                g_gval[(((size_t)b * HH + h) * DHH + d) * GG + g] = v;
            } else {
                int d2 = n - 512;
                g_lk[((size_t)b * DD + d2) * GG + g] = v;
            }
        }
    }
}

// ---------------- kernel 3: 512-step decode, cluster of 2 CTAs per batch row
__global__ void __launch_bounds__(640, 1) __cluster_dims__(2, 1, 1)
decode_kernel(const float* __restrict__ emb, const float* __restrict__ Wstep,
              const float* __restrict__ Wout, const int* __restrict__ n_steps_p,
              float* __restrict__ out, int has_pi) {

    cg::cluster_group cl = cg::this_cluster();
    const int rank = (int)(blockIdx.x & 1);
    const int b = blockIdx.x >> 1;
    const int goff = rank * GH;
    const int tid = threadIdx.x;            // 640 threads = 20 warps
    const int warp = tid >> 5, lane = tid & 31;
    const int T = n_steps_p[0];

    __shared__ float fixed_s[DD], prev_s[DD], q_s[DD], heads_s[DD], glimpse_s[DD];
    __shared__ float w_s[HH][GH];           // compat->exp weights; reused as logit partials
    __shared__ float qpart8[8][DD];         // split-K projection partials
    __shared__ float logits_s[GH];
    __shared__ float rmax_s[HH];            // LOCAL row max
    __shared__ float red_s[20];
    __shared__ int   red_i[20];
    __shared__ float mloc_s, lse_s;
    __shared__ int   sel_s;
    __shared__ unsigned char visited_s[GH];
    // ---- DSMEM exchange buffers (peer reads these) ----
    __shared__ float exc_q[DD];
    __shared__ float exc_heads[DD];
    __shared__ float exc_gl[DD];
    __shared__ float exc_max[HH];
    __shared__ float exc_sum[HH];
    __shared__ float exc_amv;
    __shared__ int   exc_ami;
    __shared__ float exc_ls;

    const int peer = rank ^ 1;
    const float* p_q     = (const float*)cl.map_shared_rank((void*)exc_q, peer);
    const float* p_heads = (const float*)cl.map_shared_rank((void*)exc_heads, peer);
    const float* p_gl    = (const float*)cl.map_shared_rank((void*)exc_gl, peer);
    const float* p_max   = (const float*)cl.map_shared_rank((void*)exc_max, peer);
    const float* p_sum   = (const float*)cl.map_shared_rank((void*)exc_sum, peer);
    const float* p_amv   = (const float*)cl.map_shared_rank((void*)&exc_amv, peer);
    const int*   p_ami   = (const int*)cl.map_shared_rank((void*)&exc_ami, peer);
    const float* p_ls    = (const float*)cl.map_shared_rank((void*)&exc_ls, peer);

    if (tid < DD) {
        fixed_s[tid] = g_fixed[b * DD + tid];
        prev_s[tid]  = g_gemb[b * DD + tid];
    }
    if (tid < GH) visited_s[tid] = 0;
    __syncthreads();

    const float* gk_b  = g_gkey + (size_t)b * HH * DHH * GG + goff;
    const float* gv_b  = g_gval + (size_t)b * HH * DHH * GG + goff;
    const float* lk_b  = g_lk   + (size_t)b * DD * GG + goff;
    const float* emb_b = emb    + (size_t)b * GG * DD;
    const float inv_sqrt_dh = 0.17677669529663687f;   // 1/sqrt(32)
    const float inv_sqrt_D  = 0.0625f;                // 1/sqrt(256)

    const int cp_h  = tid / 80;          // head (compat) / d-group (logits)
    const int cp_g4 = (tid % 80) * 4;    // local g quad base
    const int pj_p  = tid >> 6;          // 0..9 (used when tid<512)
    const int pj_cq = (tid & 63) * 4;

    for (int t = 0; t < T; ++t) {
        // ======== q = fixed + prev @ Wstep : split-K across cluster ========
        if (tid < 512) {
            const int kbase = rank * 128 + pj_p * 16;
            const float* wp = Wstep + (size_t)kbase * DD + pj_cq;
            const float* pv = prev_s + kbase;
            float4 a0 = make_float4(0.f, 0.f, 0.f, 0.f);
            float4 a1 = make_float4(0.f, 0.f, 0.f, 0.f);
            #pragma unroll
            for (int i = 0; i < 16; i += 2) {
                float v0 = pv[i], v1 = pv[i + 1];
                float4 w0 = *(const float4*)(wp + (size_t)i * DD);
                float4 w1 = *(const float4*)(wp + (size_t)(i + 1) * DD);
                a0.x = fmaf(v0, w0.x, a0.x); a0.y = fmaf(v0, w0.y, a0.y);
                a0.z = fmaf(v0, w0.z, a0.z); a0.w = fmaf(v0, w0.w, a0.w);
                a1.x = fmaf(v1, w1.x, a1.x); a1.y = fmaf(v1, w1.y, a1.y);
                a1.z = fmaf(v1, w1.z, a1.z); a1.w = fmaf(v1, w1.w, a1.w);
            }
            float4 r;
            r.x = a0.x + a1.x; r.y = a0.y + a1.y; r.z = a0.z + a1.z; r.w = a0.w + a1.w;
            *(float4*)&qpart8[pj_p][pj_cq] = r;
        }
        __syncthreads();
        if (tid < DD) {
            float s = 0.f;
            #pragma unroll
            for (int p = 0; p < 8; ++p) s += qpart8[p][tid];
            exc_q[tid] = s;
        }
        cl.sync();                                   // S1
        if (tid < DD) {
            float lo = rank == 0 ? exc_q[tid] : p_q[tid];
            float hi = rank == 0 ? p_q[tid] : exc_q[tid];
            q_s[tid] = fixed_s[tid] + lo + hi;       // rank-independent order
        }
        __syncthreads();

        // ======== compat over my 320 g's, all 8 heads ========
        {
            unsigned char v0 = visited_s[cp_g4 + 0], v1 = visited_s[cp_g4 + 1];
            unsigned char v2 = visited_s[cp_g4 + 2], v3 = visited_s[cp_g4 + 3];
            const float* base = gk_b + (size_t)cp_h * DHH * GG + cp_g4;
            const float* qh = q_s + cp_h * DHH;
            float ax = 0.f, ay = 0.f, az = 0.f, aw = 0.f;
            #pragma unroll
            for (int d = 0; d < DHH; ++d) {
                float4 kk = *(const float4*)(base + (size_t)d * GG);
                float qd = qh[d];
                ax = fmaf(qd, kk.x, ax);
                ay = fmaf(qd, kk.y, ay);
                az = fmaf(qd, kk.z, az);
                aw = fmaf(qd, kk.w, aw);
            }
            float4 r;
            r.x = v0 ? NEGINF : ax * inv_sqrt_dh;
            r.y = v1 ? NEGINF : ay * inv_sqrt_dh;
            r.z = v2 ? NEGINF : az * inv_sqrt_dh;
            r.w = v3 ? NEGINF : aw * inv_sqrt_dh;
            *(float4*)&w_s[cp_h][cp_g4] = r;
        }
        __syncthreads();

        // ======== LOCAL row max (no cluster exchange needed) ========
        if (warp < 16) {
            const int h = warp >> 1, half = warp & 1;
            const float* row = &w_s[h][half * 160];
            float m = -3e38f;
            #pragma unroll
            for (int k = 0; k < 5; ++k) m = fmaxf(m, row[lane + k * 32]);
            #pragma unroll
            for (int o = 16; o; o >>= 1) m = fmaxf(m, __shfl_xor_sync(0xffffffffu, m, o));
            if (lane == 0) red_s[warp] = m;
        }
        __syncthreads();
        if (tid < HH) {
            float m = fmaxf(red_s[tid * 2], red_s[tid * 2 + 1]);
            rmax_s[tid] = m;
            exc_max[tid] = m;
        }
        __syncthreads();

        // ======== exp(x - LOCAL max) + local sums ========
        if (warp < 16) {
            const int h = warp >> 1, half = warp & 1;
            const float rm = rmax_s[h];
            float* row = &w_s[h][half * 160];
            float s = 0.f;
            #pragma unroll
            for (int k = 0; k < 5; ++k) {
                float e = expf(row[lane + k * 32] - rm);
                row[lane + k * 32] = e;
                s += e;
            }
            #pragma unroll
            for (int o = 16; o; o >>= 1) s += __shfl_xor_sync(0xffffffffu, s, o);
            if (lane == 0) red_s[warp] = s;
        }
        __syncthreads();
        if (tid < HH) exc_sum[tid] = red_s[tid * 2] + red_s[tid * 2 + 1];

        // ======== heads partials over my 320 g's (gval STREAMED via ld.cs) ====
        if (warp < 16) {
            #pragma unroll 2
            for (int r = 0; r < 16; ++r) {
                const int row = warp * 16 + r;        // row = h*32 + d
                const int h = row >> 5;
                const float* vrow = gv_b + (size_t)row * GG;
                const float* wrow = &w_s[h][0];
                float ax = 0.f, ay = 0.f, az = 0.f, aw = 0.f;
                #pragma unroll
                for (int c = 0; c < 3; ++c) {
                    int u = lane + c * 32;            // float4 unit, 80 total
                    if (u < 80) {
                        float4 vv = __ldcs((const float4*)(vrow + u * 4));
                        float4 ww = *(const float4*)(wrow + u * 4);
                        ax = fmaf(ww.x, vv.x, ax);
                        ay = fmaf(ww.y, vv.y, ay);
                        az = fmaf(ww.z, vv.z, az);
                        aw = fmaf(ww.w, vv.w, aw);
                    }
                }
                float s = (ax + ay) + (az + aw);
                #pragma unroll
                for (int o = 16; o; o >>= 1) s += __shfl_xor_sync(0xffffffffu, s, o);
                if (lane == 0) exc_heads[row] = s;
            }
        }
        cl.sync();                                   // S2 (max + sums + head partials)
        if (tid < DD) {
            const int h = tid >> 5;
            float m_lo = rank == 0 ? exc_max[h] : p_max[h];
            float m_hi = rank == 0 ? p_max[h] : exc_max[h];
            float Mg = fmaxf(m_lo, m_hi);
            float e_lo = expf(m_lo - Mg), e_hi = expf(m_hi - Mg);
            float h_lo = rank == 0 ? exc_heads[tid] : p_heads[tid];
            float h_hi = rank == 0 ? p_heads[tid] : exc_heads[tid];
            float s_lo = rank == 0 ? exc_sum[h] : p_sum[h];
            float s_hi = rank == 0 ? p_sum[h] : exc_sum[h];
            heads_s[tid] = (h_lo * e_lo + h_hi * e_hi) / (s_lo * e_lo + s_hi * e_hi);
        }
        __syncthreads();

        // ======== glimpse = heads @ Wout : split-K across cluster ========
        if (tid < 512) {
            const int kbase = rank * 128 + pj_p * 16;
            const float* wp = Wout + (size_t)kbase * DD + pj_cq;
            const float* hv = heads_s + kbase;
            float4 a0 = make_float4(0.f, 0.f, 0.f, 0.f);
            float4 a1 = make_float4(0.f, 0.f, 0.f, 0.f);
            #pragma unroll
            for (int i = 0; i < 16; i += 2) {
                float v0 = hv[i], v1 = hv[i + 1];
                float4 w0 = *(const float4*)(wp + (size_t)i * DD);
                float4 w1 = *(const float4*)(wp + (size_t)(i + 1) * DD);
                a0.x = fmaf(v0, w0.x, a0.x); a0.y = fmaf(v0, w0.y, a0.y);
                a0.z = fmaf(v0, w0.z, a0.z); a0.w = fmaf(v0, w0.w, a0.w);
                a1.x = fmaf(v1, w1.x, a1.x); a1.y = fmaf(v1, w1.y, a1.y);
                a1.z = fmaf(v1, w1.z, a1.z); a1.w = fmaf(v1, w1.w, a1.w);
            }
            float4 r;
            r.x = a0.x + a1.x; r.y = a0.y + a1.y; r.z = a0.z + a1.z; r.w = a0.w + a1.w;
            *(float4*)&qpart8[pj_p][pj_cq] = r;
        }
        __syncthreads();
        if (tid < DD) {
            float s = 0.f;
            #pragma unroll
            for (int p = 0; p < 8; ++p) s += qpart8[p][tid];
            exc_gl[tid] = s;
        }
        cl.sync();                                   // S3
        if (tid < DD) {
            float lo = rank == 0 ? exc_gl[tid] : p_gl[tid];
            float hi = rank == 0 ? p_gl[tid] : exc_gl[tid];
            glimpse_s[tid] = lo + hi;
        }
        __syncthreads();

        // ======== logits partials: 8 d-groups x 80 g-quads (into w_s) ========
        {
            const float* base = lk_b + (size_t)(cp_h * 32) * GG + cp_g4;
            const float* gl = glimpse_s + cp_h * 32;
            float ax = 0.f, ay = 0.f, az = 0.f, aw = 0.f;
            #pragma unroll 8
            for (int d = 0; d < 32; ++d) {
                float4 kk = *(const float4*)(base + (size_t)d * GG);
                float gv2 = gl[d];
                ax = fmaf(gv2, kk.x, ax);
                ay = fmaf(gv2, kk.y, ay);
                az = fmaf(gv2, kk.z, az);
                aw = fmaf(gv2, kk.w, aw);
            }
            float4 r; r.x = ax; r.y = ay; r.z = az; r.w = aw;
            *(float4*)&w_s[cp_h][cp_g4] = r;
        }
        __syncthreads();
        if (tid < GH) {
            float l = ((w_s[0][tid] + w_s[1][tid]) + (w_s[2][tid] + w_s[3][tid]))
                    + ((w_s[4][tid] + w_s[5][tid]) + (w_s[6][tid] + w_s[7][tid]));
            l = 10.0f * tanhf(l * inv_sqrt_D);
            logits_s[tid] = visited_s[tid] ? NEGINF : l;
        }
        __syncthreads();

        // ======== local argmax over my 320 (first occurrence, global idx) ====
        if (tid < GH) {
            float v = logits_s[tid];
            int idx = goff + tid;
            #pragma unroll
            for (int o = 16; o; o >>= 1) {
                float ov = __shfl_xor_sync(0xffffffffu, v, o);
                int oi = __shfl_xor_sync(0xffffffffu, idx, o);
                if (ov > v || (ov == v && oi < idx)) { v = ov; idx = oi; }
            }
            if (lane == 0) { red_s[warp] = v; red_i[warp] = idx; }
        }
        __syncthreads();
        if (tid == 0) {
            float v = red_s[0]; int idx = red_i[0];
            #pragma unroll
            for (int wv = 1; wv < 10; ++wv) {
                if (red_s[wv] > v || (red_s[wv] == v && red_i[wv] < idx)) {
                    v = red_s[wv]; idx = red_i[wv];
                }
            }
            exc_amv = v; exc_ami = idx; mloc_s = v;   // local max
        }
        __syncthreads();
        const float mloc = mloc_s;
        // local sumexp at LOCAL max
        if (tid < GH) {
            float e = expf(logits_s[tid] - mloc);
            #pragma unroll
            for (int o = 16; o; o >>= 1) e += __shfl_xor_sync(0xffffffffu, e, o);
            if (lane == 0) red_s[warp] = e;
        }
        __syncthreads();
        if (tid == 0) {
            float s = 0.f;
            #pragma unroll
            for (int wv = 0; wv < 10; ++wv) s += red_s[wv];
            exc_ls = s;
        }
        cl.sync();                                   // S4 (argmax + lse merged)
        if (tid == 0) {
            float m0 = rank == 0 ? exc_amv : *p_amv;
            int   i0 = rank == 0 ? exc_ami : *p_ami;
            float s0 = rank == 0 ? exc_ls  : *p_ls;
            float m1 = rank == 0 ? *p_amv : exc_amv;
            int   i1 = rank == 0 ? *p_ami : exc_ami;
            float s1 = rank == 0 ? *p_ls  : exc_ls;
            int sel = (m1 > m0 || (m1 == m0 && i1 < i0)) ? i1 : i0;
            float Mg = fmaxf(m0, m1);
            float lse = Mg + logf(s0 * expf(m0 - Mg) + s1 * expf(m1 - Mg));
            sel_s = sel; lse_s = lse;
        }
        __syncthreads();
        const float lse = lse_s;
        const int sel = sel_s;

        // ======== outputs (streaming stores) ========
        if (tid < GH)
            __stcs(&out[((size_t)b * T + t) * GG + goff + tid], logits_s[tid] - lse);
        if (has_pi && rank == 0 && tid == 0)
            __stcs(&out[(size_t)BB * T * GG + (size_t)b * T + t], (float)sel);

        // ======== state update ========
        if (tid == 0 && (sel >> 5) / 10 == rank)     // sel/320 == rank
            visited_s[sel - goff] = 1;
        if (tid < DD) prev_s[tid] = __ldcs(&emb_b[(size_t)sel * DD + tid]);
        __syncthreads();
    }
}

// ---------------- launch ----------------
extern "C" void kernel_launch(void* const* d_in, const int* in_sizes, int n_in,
                              void* d_out, int out_size) {
    const float* emb    = (const float*)d_in[0];
    const float* Wnode  = (const float*)d_in[1];
    const float* Wfixed = (const float*)d_in[2];
    const float* Wstep  = (const float*)d_in[3];
    const float* Wout   = (const float*)d_in[4];
    const int*   nsteps = (const int*)d_in[5];
    float* out = (float*)d_out;

    int has_pi = (out_size % (BB * (GG + 1)) == 0) ? 1 : 0;

    mean_fixed_kernel<<<BB, DD>>>(emb, Wfixed);

    dim3 ggrid(12, 640);      // 768/64 x 40960/64
    kvl_gemm<<<ggrid, 256>>>(emb, Wnode);

    decode_kernel<<<BB * 2, GG>>>(emb, Wstep, Wout, nsteps, out, has_pi);
}